// round 14
// baseline (speedup 1.0000x reference)
#include <cuda_runtime.h>
#include <cuda_bf16.h>
#include <math.h>
#include <stdint.h>

#define CCH 180
#define FCD 540           // 3*C
#define HID 1620          // 3*FC
#define NGR 2048
#define LNUM 6
#define MAXN 50000
#define MAXE 150000

// ---------------- scratch (device globals; no allocation allowed) ----------------
__device__ float g_h  [3][MAXN * CCH];
__device__ float g_hn [3][MAXN * CCH];
__device__ float g_m  [3][MAXN * CCH];
__device__ float g_agg [3][MAXN * CCH];   // ping
__device__ float g_agg2[3][MAXN * CCH];   // pong
__device__ float g_pool[NGR * FCD];
__device__ float g_cnt [3 * NGR];
__device__ float g_x  [NGR * FCD];
__device__ float g_b1 [NGR * HID];
__device__ float g_b2 [NGR * HID];

// pre-converted (tf32-rounded) weights
#define OFF_CONV 0
#define OFF_WIH  972000
#define OFF_WHH  1263600
#define OFF_FC1  1555200
#define OFF_FC2  2430000
#define OFF_FC25 5054400
#define OFF_FC3  5929200
#define WTF_TOTAL 5930820
__device__ float g_wtf[WTF_TOTAL];

// ---------------- tf32 helpers ----------------
__device__ __forceinline__ uint32_t f2tf32(float f) {
    uint32_t u;
    asm("cvt.rna.tf32.f32 %0, %1;" : "=r"(u) : "f"(f));
    return u;
}

__device__ __forceinline__ void mma_tf32(float* c, const uint32_t* a, const uint32_t* b) {
    asm volatile(
        "mma.sync.aligned.m16n8k8.row.col.f32.tf32.tf32.f32 "
        "{%0,%1,%2,%3}, {%4,%5,%6,%7}, {%8,%9}, {%0,%1,%2,%3};"
        : "+f"(c[0]), "+f"(c[1]), "+f"(c[2]), "+f"(c[3])
        : "r"(a[0]), "r"(a[1]), "r"(a[2]), "r"(a[3]), "r"(b[0]), "r"(b[1]));
}

__device__ __forceinline__ void ldsm_x4(uint32_t& r0, uint32_t& r1, uint32_t& r2, uint32_t& r3,
                                        uint32_t saddr) {
    asm volatile("ldmatrix.sync.aligned.m8n8.x4.shared.b16 {%0,%1,%2,%3}, [%4];"
                 : "=r"(r0), "=r"(r1), "=r"(r2), "=r"(r3) : "r"(saddr));
}

__device__ __forceinline__ void cp_async16(uint32_t saddr, const void* gptr, int src_bytes) {
    asm volatile("cp.async.cg.shared.global [%0], [%1], 16, %2;"
                 :: "r"(saddr), "l"(gptr), "r"(src_bytes));
}
__device__ __forceinline__ void cp_commit() { asm volatile("cp.async.commit_group;"); }
__device__ __forceinline__ void cp_wait0()  { asm volatile("cp.async.wait_group 0;"); }

__device__ __forceinline__ float sigm(float x) { return 1.f / (1.f + __expf(-x)); }

// ---------------- generic tf32 tensor-core GEMM (verbatim R8/R12) ----------------
template<int TRANSB, int RELU, int BIAS>
__global__ __launch_bounds__(256)
void gemm_tf32(const float* __restrict__ A, const float* __restrict__ B,
               const float* __restrict__ bias, float* __restrict__ C,
               int N, int K, int M, int lda)
{
    __shared__ uint4 As4[2][128 * 8];
    __shared__ uint4 Bs4[2][64 * 8];

    const int tid  = threadIdx.x;
    const int lane = tid & 31;
    const int wid  = tid >> 5;
    const int wm   = (wid & 1) * 64;
    const int wn   = (wid >> 1) * 16;
    const int n0   = blockIdx.x * 128;
    const int m0   = blockIdx.y * 64;

    float acc[4][2][4];
    #pragma unroll
    for (int i = 0; i < 4; i++)
        #pragma unroll
        for (int j = 0; j < 2; j++)
            #pragma unroll
            for (int q = 0; q < 4; q++) acc[i][j][q] = 0.f;

    const int arow = tid >> 1;
    const int ac0  = (tid & 1) * 4;
    const bool arow_ok = (n0 + arow) < N;
    const float* Ap = A + (size_t)(n0 + arow) * lda;

    float4 pa[4];
    float4 pbnn[2];

    auto loadA = [&](int k0) {
        #pragma unroll
        for (int c = 0; c < 4; c++) {
            int gk = k0 + (ac0 + c) * 4;
            pa[c] = make_float4(0.f, 0.f, 0.f, 0.f);
            if (arow_ok && gk < K)
                pa[c] = *reinterpret_cast<const float4*>(Ap + gk);
        }
    };
    auto storeA = [&](int st) {
        #pragma unroll
        for (int c = 0; c < 4; c++) {
            int kc = ac0 + c;
            uint4 u;
            u.x = f2tf32(pa[c].x); u.y = f2tf32(pa[c].y);
            u.z = f2tf32(pa[c].z); u.w = f2tf32(pa[c].w);
            As4[st][(arow << 3) + (kc ^ (arow & 7))] = u;
        }
    };

    auto issueB_nt = [&](int k0, int st) {
        uint32_t sb = (uint32_t)__cvta_generic_to_shared(&Bs4[st][0]);
        #pragma unroll
        for (int i = 0; i < 2; i++) {
            int cid = tid * 2 + i;
            int m  = cid >> 3;
            int kc = cid & 7;
            int gm = m0 + m, gk = k0 + kc * 4;
            const float* gp = B + (size_t)gm * K + gk;
            int ok = (gm < M && gk < K) ? 16 : 0;
            cp_async16(sb + (((m << 3) + (kc ^ (m & 7))) << 4), gp, ok);
        }
    };
    auto loadB_nn = [&](int k0) {
        #pragma unroll
        for (int i = 0; i < 2; i++) {
            int s = tid + i * 256;
            int kc = s >> 6, m = s & 63;
            int gm = m0 + m;
            float* d = &pbnn[i].x;
            #pragma unroll
            for (int q = 0; q < 4; q++) {
                int gk = k0 + kc * 4 + q;
                d[q] = (gm < M && gk < K) ? B[(size_t)gk * M + gm] : 0.f;
            }
        }
    };
    auto storeB_nn = [&](int st) {
        #pragma unroll
        for (int i = 0; i < 2; i++) {
            int s = tid + i * 256;
            int kc = s >> 6, m = s & 63;
            uint4 u;
            u.x = __float_as_uint(pbnn[i].x); u.y = __float_as_uint(pbnn[i].y);
            u.z = __float_as_uint(pbnn[i].z); u.w = __float_as_uint(pbnn[i].w);
            Bs4[st][(m << 3) + (kc ^ (m & 7))] = u;
        }
    };

    const int g  = lane >> 3;
    const int l7 = lane & 7;

    auto compute = [&](int st) {
        uint32_t aBase = (uint32_t)__cvta_generic_to_shared(&As4[st][0]);
        uint32_t bBase = (uint32_t)__cvta_generic_to_shared(&Bs4[st][0]);
        #pragma unroll
        for (int kb = 0; kb < 32; kb += 8) {
            const int kq = kb >> 2;
            uint32_t a[4][4];
            #pragma unroll
            for (int i = 0; i < 4; i++) {
                int row = wm + i * 16 + ((g & 1) << 3) + l7;
                int kc  = kq + (g >> 1);
                uint32_t ad = aBase + (((row << 3) + (kc ^ (row & 7))) << 4);
                ldsm_x4(a[i][0], a[i][1], a[i][2], a[i][3], ad);
            }
            uint32_t b[4];
            {
                int nrow = wn + ((g >> 1) << 3) + l7;
                int kc   = kq + (g & 1);
                uint32_t bd = bBase + (((nrow << 3) + (kc ^ (nrow & 7))) << 4);
                ldsm_x4(b[0], b[1], b[2], b[3], bd);
            }
            #pragma unroll
            for (int i = 0; i < 4; i++) {
                mma_tf32(acc[i][0], a[i], &b[0]);
                mma_tf32(acc[i][1], a[i], &b[2]);
            }
        }
    };

    const int T = (K + 31) / 32;

    loadA(0);
    if (TRANSB) issueB_nt(0, 0); else loadB_nn(0);
    storeA(0);
    if (!TRANSB) storeB_nn(0);
    if (TRANSB) { cp_commit(); cp_wait0(); }
    __syncthreads();

    for (int kt = 0; kt < T; kt++) {
        const int cur = kt & 1, nxt = cur ^ 1;
        const bool more = (kt + 1) < T;
        if (more) {
            loadA((kt + 1) * 32);
            if (TRANSB) { issueB_nt((kt + 1) * 32, nxt); cp_commit(); }
            else loadB_nn((kt + 1) * 32);
        }
        compute(cur);
        if (more) {
            storeA(nxt);
            if (!TRANSB) storeB_nn(nxt);
            if (TRANSB) cp_wait0();
            __syncthreads();
        }
    }

    #pragma unroll
    for (int i = 0; i < 4; i++) {
        #pragma unroll
        for (int j = 0; j < 2; j++) {
            int r0 = n0 + wm + i * 16 + (lane >> 2);
            int c0 = m0 + wn + j * 8 + (lane & 3) * 2;
            if (c0 >= M) continue;
            bool c1ok = (c0 + 1) < M;
            float bv0 = BIAS ? bias[c0] : 0.f;
            float bv1 = (BIAS && c1ok) ? bias[c0 + 1] : 0.f;
            #pragma unroll
            for (int hrow = 0; hrow < 2; hrow++) {
                int r = r0 + hrow * 8;
                if (r >= N) continue;
                float v0 = acc[i][j][hrow * 2 + 0] + bv0;
                float v1 = acc[i][j][hrow * 2 + 1] + bv1;
                if (RELU) { v0 = fmaxf(v0, 0.f); v1 = fmaxf(v1, 0.f); }
                if (c1ok && ((M & 1) == 0)) {
                    *reinterpret_cast<float2*>(C + (size_t)r * M + c0) = make_float2(v0, v1);
                } else {
                    C[(size_t)r * M + c0] = v0;
                    if (c1ok) C[(size_t)r * M + c0 + 1] = v1;
                }
            }
        }
    }
}

// ---------------- fused GRU kernel: 128 rows x 64 cols, 512 threads (R12) ----------
// POOL=0: write hnew AND zero the *other* agg buffer (ping-pong — never the one read).
// POOL=1: last layer — relu + mean-pool accumulate instead (no zeroing needed).
#define GRU_STAGE_U4 5120
#define GRU_SMEM (2 * GRU_STAGE_U4 * 16)
template<int POOL>
__global__ __launch_bounds__(512, 1)
void gru_fused(const float* __restrict__ Aagg, const float* __restrict__ Ah,
               const float* __restrict__ Wih, const float* __restrict__ Whh,
               const float* __restrict__ bih, const float* __restrict__ bhh,
               float* __restrict__ hnew, float* __restrict__ aggz, int N,
               const int* __restrict__ batch, float* __restrict__ pool, int comp)
{
    extern __shared__ uint4 sm[];
    const int tid  = threadIdx.x;
    const int lane = tid & 31;
    const int wid  = tid >> 5;
    const int wm   = (wid & 3) * 32;      // 4 row groups over 128
    const int wn   = (wid >> 2) * 16;     // 4 col groups over 64
    const int n0   = blockIdx.x * 128;
    const int m0   = blockIdx.y * 64;

    float acc_i[3][2][2][4];
    float acc_h[3][2][2][4];
    #pragma unroll
    for (int gi = 0; gi < 3; gi++)
        #pragma unroll
        for (int i = 0; i < 2; i++)
            #pragma unroll
            for (int j = 0; j < 2; j++)
                #pragma unroll
                for (int q = 0; q < 4; q++) { acc_i[gi][i][j][q] = 0.f; acc_h[gi][i][j][q] = 0.f; }

    const int arow = tid >> 2;            // 0..127
    const int ac0  = (tid & 3) * 2;
    const bool arow_ok = (n0 + arow) < N;
    const float* Aggp = Aagg + (size_t)(n0 + arow) * CCH;
    const float* Ahp  = Ah   + (size_t)(n0 + arow) * CCH;

    float4 pagg[2], ph[2];

    auto loadA = [&](int k0) {
        #pragma unroll
        for (int c = 0; c < 2; c++) {
            int gk = k0 + (ac0 + c) * 4;
            pagg[c] = make_float4(0.f, 0.f, 0.f, 0.f);
            ph[c]   = make_float4(0.f, 0.f, 0.f, 0.f);
            if (arow_ok && gk < CCH) {
                pagg[c] = *reinterpret_cast<const float4*>(Aggp + gk);
                ph[c]   = *reinterpret_cast<const float4*>(Ahp + gk);
            }
        }
    };
    auto storeA = [&](int st) {
        uint4* Sa = sm + st * GRU_STAGE_U4;
        uint4* Sh = Sa + 1024;
        #pragma unroll
        for (int c = 0; c < 2; c++) {
            int kc = ac0 + c;
            int idx = (arow << 3) + (kc ^ (arow & 7));
            uint4 u;
            u.x = f2tf32(pagg[c].x); u.y = f2tf32(pagg[c].y);
            u.z = f2tf32(pagg[c].z); u.w = f2tf32(pagg[c].w);
            Sa[idx] = u;
            u.x = f2tf32(ph[c].x); u.y = f2tf32(ph[c].y);
            u.z = f2tf32(ph[c].z); u.w = f2tf32(ph[c].w);
            Sh[idx] = u;
        }
    };
    auto issueB = [&](int k0, int st) {
        uint32_t sb = (uint32_t)__cvta_generic_to_shared(sm + st * GRU_STAGE_U4 + 2048);
        const int row = tid >> 3;     // 0..63
        const int kc  = tid & 7;
        const int gm  = m0 + row;
        const int gk  = k0 + kc * 4;
        #pragma unroll
        for (int mat = 0; mat < 6; mat++) {
            const float* W = (mat < 3) ? Wih : Whh;
            int goff = (mat % 3) * CCH;
            int ok = (gm < CCH && gk < CCH) ? 16 : 0;
            cp_async16(sb + ((mat * 512 + (row << 3) + (kc ^ (row & 7))) << 4),
                       W + (size_t)(goff + gm) * CCH + gk, ok);
        }
    };

    const int g  = lane >> 3;
    const int l7 = lane & 7;

    auto compute = [&](int st) {
        uint32_t aBase = (uint32_t)__cvta_generic_to_shared(sm + st * GRU_STAGE_U4);
        uint32_t hBase = aBase + 1024 * 16;
        uint32_t bBase = aBase + 2048 * 16;
        #pragma unroll
        for (int kb = 0; kb < 32; kb += 8) {
            const int kq = kb >> 2;
            uint32_t ag[2][4], ah[2][4];
            #pragma unroll
            for (int i = 0; i < 2; i++) {
                int row = wm + i * 16 + ((g & 1) << 3) + l7;
                int kc  = kq + (g >> 1);
                uint32_t off = ((row << 3) + (kc ^ (row & 7))) << 4;
                ldsm_x4(ag[i][0], ag[i][1], ag[i][2], ag[i][3], aBase + off);
                ldsm_x4(ah[i][0], ah[i][1], ah[i][2], ah[i][3], hBase + off);
            }
            uint32_t b[6][4];
            {
                int nrow = wn + ((g >> 1) << 3) + l7;
                int kc   = kq + (g & 1);
                uint32_t off = ((nrow << 3) + (kc ^ (nrow & 7))) << 4;
                #pragma unroll
                for (int mat = 0; mat < 6; mat++)
                    ldsm_x4(b[mat][0], b[mat][1], b[mat][2], b[mat][3],
                            bBase + (mat * 512 << 4) + off);
            }
            #pragma unroll
            for (int gi = 0; gi < 3; gi++)
                #pragma unroll
                for (int i = 0; i < 2; i++) {
                    mma_tf32(acc_i[gi][i][0], ag[i], &b[gi][0]);
                    mma_tf32(acc_i[gi][i][1], ag[i], &b[gi][2]);
                    mma_tf32(acc_h[gi][i][0], ah[i], &b[3 + gi][0]);
                    mma_tf32(acc_h[gi][i][1], ah[i], &b[3 + gi][2]);
                }
        }
    };

    const int T = (CCH + 31) / 32;

    loadA(0); issueB(0, 0);
    storeA(0);
    cp_commit(); cp_wait0();
    __syncthreads();

    for (int kt = 0; kt < T; kt++) {
        const int cur = kt & 1, nxt = cur ^ 1;
        const bool more = (kt + 1) < T;
        if (more) {
            loadA((kt + 1) * 32);
            issueB((kt + 1) * 32, nxt);
            cp_commit();
        }
        compute(cur);
        if (more) {
            storeA(nxt);
            cp_wait0();
            __syncthreads();
        }
    }

    #pragma unroll
    for (int i = 0; i < 2; i++) {
        #pragma unroll
        for (int j = 0; j < 2; j++) {
            int rbase = n0 + wm + i * 16 + (lane >> 2);
            int c0 = m0 + wn + j * 8 + (lane & 3) * 2;
            #pragma unroll
            for (int q = 0; q < 2; q++) {
                int r = rbase + q * 8;
                if (r >= N) continue;
                #pragma unroll
                for (int p = 0; p < 2; p++) {
                    int c = c0 + p;
                    if (c >= CCH) continue;
                    int v = q * 2 + p;
                    float ir = acc_i[0][i][j][v] + bih[c];
                    float iz = acc_i[1][i][j][v] + bih[c + CCH];
                    float in = acc_i[2][i][j][v] + bih[c + 2 * CCH];
                    float hr = acc_h[0][i][j][v] + bhh[c];
                    float hz = acc_h[1][i][j][v] + bhh[c + CCH];
                    float hn = acc_h[2][i][j][v] + bhh[c + 2 * CCH];
                    float rg = sigm(ir + hr);
                    float z  = sigm(iz + hz);
                    float nn = tanhf(in + rg * hn);
                    float ho = Ah[(size_t)r * CCH + c];
                    float hv = (1.f - z) * nn + z * ho;
                    if (POOL) {
                        float pv = fmaxf(hv, 0.f);
                        float* pp = pool + (size_t)batch[r] * FCD + comp * CCH + c;
                        asm volatile("red.global.add.f32 [%0], %1;" :: "l"(pp), "f"(pv) : "memory");
                    } else {
                        hnew[(size_t)r * CCH + c] = hv;
                        aggz[(size_t)r * CCH + c] = 0.f;   // ping-pong buffer: safe
                    }
                }
            }
        }
    }
}

// ---------------- weight pre-conversion ----------------
__global__ void cvt_tf32_kernel(const float* __restrict__ in, float* __restrict__ out, int n)
{
    int i = blockIdx.x * blockDim.x + threadIdx.x;
    if (i < n) out[i] = __uint_as_float(f2tf32(in[i]));
}

// ---------------- elementwise / graph kernels ----------------
__global__ void pad_kernel(const float4* __restrict__ x, float4* __restrict__ h, int N, int F4)
{
    int i = blockIdx.x * blockDim.x + threadIdx.x;
    if (i >= N * 45) return;
    int n = i / 45, c = i - n * 45;
    float4 v = make_float4(0.f, 0.f, 0.f, 0.f);
    if (c < F4) v = x[(size_t)n * F4 + c];
    h[i] = v;
}

__global__ void zero_kernel(float4* __restrict__ p, int n4)
{
    int i = blockIdx.x * blockDim.x + threadIdx.x;
    if (i < n4) p[i] = make_float4(0.f, 0.f, 0.f, 0.f);
}

__global__ void scatter_kernel(const float* __restrict__ msg, const int* __restrict__ ei,
                               float* __restrict__ agg, int E)
{
    int i = blockIdx.x * blockDim.x + threadIdx.x;
    if (i >= E * 45) return;
    int e = i / 45, c = i - e * 45;
    int src = ei[e];
    int dst = ei[E + e];
    float4 v = reinterpret_cast<const float4*>(msg + (size_t)src * CCH)[c];
    float* p = agg + (size_t)dst * CCH + c * 4;
    asm volatile("red.global.add.v4.f32 [%0], {%1,%2,%3,%4};"
                 :: "l"(p), "f"(v.x), "f"(v.y), "f"(v.z), "f"(v.w) : "memory");
}

__global__ void count_kernel(const int* __restrict__ batch, float* __restrict__ cnt, int N)
{
    int i = blockIdx.x * blockDim.x + threadIdx.x;
    if (i < N) atomicAdd(&cnt[batch[i]], 1.f);
}

__global__ void bn_kernel(const float* __restrict__ pool, const float* __restrict__ cnt,
                          const float* __restrict__ gamma, const float* __restrict__ beta,
                          const float* __restrict__ mean, const float* __restrict__ var,
                          float* __restrict__ xout)
{
    int i = blockIdx.x * blockDim.x + threadIdx.x;
    if (i >= NGR * FCD) return;
    int b = i / FCD, j = i - b * FCD;
    int comp = j / CCH;
    float cn = fmaxf(cnt[comp * NGR + b], 1.f);
    float v = pool[i] / cn;
    v = (v - mean[j]) * rsqrtf(var[j] + 1e-5f) * gamma[j] + beta[j];
    xout[i] = v;
}

// ---------------- host orchestration ----------------
static inline void launch_gemm_nn(const float* A, const float* B, float* C,
                                  int N, int K, int M, int lda, cudaStream_t s)
{
    dim3 grid((N + 127) / 128, (M + 63) / 64);
    gemm_tf32<0, 0, 0><<<grid, 256, 0, s>>>(A, B, nullptr, C, N, K, M, lda);
}
template<int RELU>
static inline void launch_gemm_nt_bias(const float* A, const float* B, const float* bias,
                                       float* C, int N, int K, int M, cudaStream_t s)
{
    dim3 grid((N + 127) / 128, (M + 63) / 64);
    gemm_tf32<1, RELU, 1><<<grid, 256, 0, s>>>(A, B, bias, C, N, K, M, K);
}

extern "C" void kernel_launch(void* const* d_in, const int* in_sizes, int n_in,
                              void* d_out, int out_size)
{
    static cudaStream_t cs[3] = {0, 0, 0};
    static cudaEvent_t ev_root = 0, ev_done[3] = {0, 0, 0};
    if (cs[0] == 0) {
        for (int i = 0; i < 3; i++) {
            cudaStreamCreateWithFlags(&cs[i], cudaStreamNonBlocking);
            cudaEventCreateWithFlags(&ev_done[i], cudaEventDisableTiming);
        }
        cudaEventCreateWithFlags(&ev_root, cudaEventDisableTiming);
        cudaFuncSetAttribute(gru_fused<0>, cudaFuncAttributeMaxDynamicSharedMemorySize, GRU_SMEM);
        cudaFuncSetAttribute(gru_fused<1>, cudaFuncAttributeMaxDynamicSharedMemorySize, GRU_SMEM);
    }
    cudaStream_t s0 = 0;

    const float* x[3]     = {(const float*)d_in[0], (const float*)d_in[3], (const float*)d_in[6]};
    const int*   ei[3]    = {(const int*)d_in[1], (const int*)d_in[4], (const int*)d_in[7]};
    const int*   batch[3] = {(const int*)d_in[2], (const int*)d_in[5], (const int*)d_in[8]};
    const float* convW = (const float*)d_in[9];
    const float* Wih   = (const float*)d_in[10];
    const float* Whh   = (const float*)d_in[11];
    const float* bih   = (const float*)d_in[12];
    const float* bhh   = (const float*)d_in[13];
    const float* bn_g  = (const float*)d_in[14];
    const float* bn_b  = (const float*)d_in[15];
    const float* bn_m  = (const float*)d_in[16];
    const float* bn_v  = (const float*)d_in[17];
    const float* fc1b  = (const float*)d_in[19];
    const float* fc2b  = (const float*)d_in[21];
    const float* fc25b = (const float*)d_in[23];
    const float* fc3b  = (const float*)d_in[25];

    const int N = in_sizes[2];
    const int E = in_sizes[1] / 2;
    const int F = in_sizes[0] / N;

    float *h_, *hn_, *m_, *agg_, *agg2_, *pool_, *cnt_, *x_, *b1_, *b2_, *wtf_;
    cudaGetSymbolAddress((void**)&h_,    g_h);
    cudaGetSymbolAddress((void**)&hn_,   g_hn);
    cudaGetSymbolAddress((void**)&m_,    g_m);
    cudaGetSymbolAddress((void**)&agg_,  g_agg);
    cudaGetSymbolAddress((void**)&agg2_, g_agg2);
    cudaGetSymbolAddress((void**)&pool_, g_pool);
    cudaGetSymbolAddress((void**)&cnt_,  g_cnt);
    cudaGetSymbolAddress((void**)&x_,    g_x);
    cudaGetSymbolAddress((void**)&b1_,   g_b1);
    cudaGetSymbolAddress((void**)&b2_,   g_b2);
    cudaGetSymbolAddress((void**)&wtf_,  g_wtf);

    const int TPB = 256;
    const int nNC4 = N * 45;
    const int gNC4 = (nNC4 + TPB - 1) / TPB;
    const int gScat = (E * 45 + TPB - 1) / TPB;

    // pre-convert all weights to tf32
    {
        const float* fc1W  = (const float*)d_in[18];
        const float* fc2W  = (const float*)d_in[20];
        const float* fc25W = (const float*)d_in[22];
        const float* fc3W  = (const float*)d_in[24];
        struct { const float* src; int off; int n; } wl[7] = {
            {convW, OFF_CONV, 3 * LNUM * CCH * CCH},
            {Wih,   OFF_WIH,  3 * FCD * CCH},
            {Whh,   OFF_WHH,  3 * FCD * CCH},
            {fc1W,  OFF_FC1,  HID * FCD},
            {fc2W,  OFF_FC2,  HID * HID},
            {fc25W, OFF_FC25, FCD * HID},
            {fc3W,  OFF_FC3,  3 * FCD},
        };
        for (int i = 0; i < 7; i++)
            cvt_tf32_kernel<<<(wl[i].n + 511) / 512, 512, 0, s0>>>(wl[i].src, wtf_ + wl[i].off, wl[i].n);
    }

    zero_kernel<<<(NGR * FCD / 4 + TPB - 1) / TPB, TPB, 0, s0>>>((float4*)pool_, NGR * FCD / 4);
    zero_kernel<<<(3 * NGR / 4 + TPB - 1) / TPB, TPB, 0, s0>>>((float4*)cnt_, 3 * NGR / 4);

    cudaEventRecord(ev_root, s0);

    const dim3 gruGrid((N + 127) / 128, 3);
    const size_t CS = (size_t)MAXN * CCH;

    for (int comp = 0; comp < 3; comp++) {
        cudaStream_t s = cs[comp];
        cudaStreamWaitEvent(s, ev_root, 0);

        float* hcur  = h_  + comp * CS;
        float* hnext = hn_ + comp * CS;
        float* mm    = m_  + comp * CS;
        float* agA   = agg_  + comp * CS;   // ping
        float* agB   = agg2_ + comp * CS;   // pong

        // step-0 agg zero (later steps are zeroed by the previous gru epilogue, ping-pong)
        zero_kernel<<<gNC4, TPB, 0, s>>>((float4*)agA, nNC4);
        pad_kernel<<<gNC4, TPB, 0, s>>>((const float4*)x[comp], (float4*)hcur, N, F / 4);
        const float* WihC = wtf_ + OFF_WIH + (size_t)comp * FCD * CCH;
        const float* WhhC = wtf_ + OFF_WHH + (size_t)comp * FCD * CCH;
        const float* bihC = bih + (size_t)comp * FCD;
        const float* bhhC = bhh + (size_t)comp * FCD;

        for (int l = 0; l < LNUM; l++) {
            const float* Wl = wtf_ + OFF_CONV + ((size_t)comp * LNUM + l) * CCH * CCH;
            int Keff = (l == 0 && (F % 4) == 0 && F < CCH) ? F : CCH;
            float* agRead  = (l & 1) ? agB : agA;    // scatter target / gru A-operand
            float* agZero  = (l & 1) ? agA : agB;    // buffer the gru epilogue zeros
            launch_gemm_nn(hcur, Wl, mm, N, Keff, CCH, CCH, s);
            scatter_kernel<<<gScat, TPB, 0, s>>>(mm, ei[comp], agRead, E);
            if (l < LNUM - 1) {
                gru_fused<0><<<gruGrid, 512, GRU_SMEM, s>>>(agRead, hcur, WihC, WhhC, bihC, bhhC,
                                                            hnext, agZero, N, nullptr, nullptr, comp);
            } else {
                gru_fused<1><<<gruGrid, 512, GRU_SMEM, s>>>(agRead, hcur, WihC, WhhC, bihC, bhhC,
                                                            nullptr, nullptr, N, batch[comp], pool_, comp);
            }
            float* t = hcur; hcur = hnext; hnext = t;
        }
        count_kernel<<<(N + TPB - 1) / TPB, TPB, 0, s>>>(batch[comp], cnt_ + comp * NGR, N);
        cudaEventRecord(ev_done[comp], s);
    }

    for (int comp = 0; comp < 3; comp++)
        cudaStreamWaitEvent(s0, ev_done[comp], 0);

    bn_kernel<<<(NGR * FCD + TPB - 1) / TPB, TPB, 0, s0>>>(pool_, cnt_, bn_g, bn_b, bn_m, bn_v, x_);

    launch_gemm_nt_bias<1>(x_,  wtf_ + OFF_FC1,  fc1b,  b1_, NGR, FCD, HID, s0);
    launch_gemm_nt_bias<1>(b1_, wtf_ + OFF_FC2,  fc2b,  b2_, NGR, HID, HID, s0);
    launch_gemm_nt_bias<1>(b2_, wtf_ + OFF_FC25, fc25b, x_,  NGR, HID, FCD, s0);
    launch_gemm_nt_bias<0>(x_,  wtf_ + OFF_FC3,  fc3b,  (float*)d_out, NGR, FCD, 3, s0);
}

// round 17
// speedup vs baseline: 1.0182x; 1.0182x over previous
#include <cuda_runtime.h>
#include <cuda_bf16.h>
#include <math.h>
#include <stdint.h>

#define CCH 180
#define FCD 540           // 3*C
#define HID 1620          // 3*FC
#define NGR 2048
#define LNUM 6
#define MAXN 50000
#define MAXE 150000

// ---------------- scratch (device globals; no allocation allowed) ----------------
__device__ float g_h  [3][MAXN * CCH];
__device__ float g_hn [3][MAXN * CCH];
__device__ float g_agg[3][MAXN * CCH];
__device__ float g_pool[NGR * FCD];
__device__ float g_cnt [3 * NGR];
__device__ float g_x  [NGR * FCD];
__device__ float g_b1 [NGR * HID];
__device__ float g_b2 [NGR * HID];

// CSR-by-src (built once per launch per component)
__device__ int g_rowptr[3][MAXN + 1];
__device__ int g_cursor[3][MAXN + 4];
__device__ int g_dst   [3][MAXE];

// pre-converted (tf32-rounded) weights; conv stored TRANSPOSED [mat][m][k]
#define OFF_CONV 0
#define OFF_WIH  972000
#define OFF_WHH  1263600
#define OFF_FC1  1555200
#define OFF_FC2  2430000
#define OFF_FC25 5054400
#define OFF_FC3  5929200
#define WTF_TOTAL 5930820
__device__ float g_wtf[WTF_TOTAL];

// ---------------- tf32 helpers ----------------
__device__ __forceinline__ uint32_t f2tf32(float f) {
    uint32_t u;
    asm("cvt.rna.tf32.f32 %0, %1;" : "=r"(u) : "f"(f));
    return u;
}

__device__ __forceinline__ void mma_tf32(float* c, const uint32_t* a, const uint32_t* b) {
    asm volatile(
        "mma.sync.aligned.m16n8k8.row.col.f32.tf32.tf32.f32 "
        "{%0,%1,%2,%3}, {%4,%5,%6,%7}, {%8,%9}, {%0,%1,%2,%3};"
        : "+f"(c[0]), "+f"(c[1]), "+f"(c[2]), "+f"(c[3])
        : "r"(a[0]), "r"(a[1]), "r"(a[2]), "r"(a[3]), "r"(b[0]), "r"(b[1]));
}

__device__ __forceinline__ void ldsm_x4(uint32_t& r0, uint32_t& r1, uint32_t& r2, uint32_t& r3,
                                        uint32_t saddr) {
    asm volatile("ldmatrix.sync.aligned.m8n8.x4.shared.b16 {%0,%1,%2,%3}, [%4];"
                 : "=r"(r0), "=r"(r1), "=r"(r2), "=r"(r3) : "r"(saddr));
}

__device__ __forceinline__ void cp_async16(uint32_t saddr, const void* gptr, int src_bytes) {
    asm volatile("cp.async.cg.shared.global [%0], [%1], 16, %2;"
                 :: "r"(saddr), "l"(gptr), "r"(src_bytes));
}
__device__ __forceinline__ void cp_commit() { asm volatile("cp.async.commit_group;"); }
__device__ __forceinline__ void cp_wait0()  { asm volatile("cp.async.wait_group 0;"); }

__device__ __forceinline__ float sigm(float x) { return 1.f / (1.f + __expf(-x)); }

__device__ __forceinline__ void red_v2(float* p, float a, float b) {
    asm volatile("red.global.add.v2.f32 [%0], {%1,%2};" :: "l"(p), "f"(a), "f"(b) : "memory");
}

// ---------------- generic tf32 tensor-core GEMM ----------------
// SCATTER=0: C[n,m] = A@B^T (+bias)(+relu).  SCATTER=1: epilogue scatters rows to agg
// via CSR out-edges (C is the agg base; rowptr/dstidx give edges). B always [m][k].
template<int RELU, int BIAS, int SCATTER>
__global__ __launch_bounds__(256)
void gemm_tf32(const float* __restrict__ A, const float* __restrict__ B,
               const float* __restrict__ bias, float* __restrict__ C,
               int N, int K, int M, int lda, int ldb,
               const int* __restrict__ rowptr, const int* __restrict__ dstidx)
{
    __shared__ uint4 As4[2][128 * 8];
    __shared__ uint4 Bs4[2][64 * 8];

    const int tid  = threadIdx.x;
    const int lane = tid & 31;
    const int wid  = tid >> 5;
    const int wm   = (wid & 1) * 64;
    const int wn   = (wid >> 1) * 16;
    const int n0   = blockIdx.x * 128;
    const int m0   = blockIdx.y * 64;

    float acc[4][2][4];
    #pragma unroll
    for (int i = 0; i < 4; i++)
        #pragma unroll
        for (int j = 0; j < 2; j++)
            #pragma unroll
            for (int q = 0; q < 4; q++) acc[i][j][q] = 0.f;

    const int arow = tid >> 1;
    const int ac0  = (tid & 1) * 4;
    const bool arow_ok = (n0 + arow) < N;
    const float* Ap = A + (size_t)(n0 + arow) * lda;

    float4 pa[4];

    auto loadA = [&](int k0) {
        #pragma unroll
        for (int c = 0; c < 4; c++) {
            int gk = k0 + (ac0 + c) * 4;
            pa[c] = make_float4(0.f, 0.f, 0.f, 0.f);
            if (arow_ok && gk < K)
                pa[c] = *reinterpret_cast<const float4*>(Ap + gk);
        }
    };
    auto storeA = [&](int st) {
        #pragma unroll
        for (int c = 0; c < 4; c++) {
            int kc = ac0 + c;
            uint4 u;
            u.x = f2tf32(pa[c].x); u.y = f2tf32(pa[c].y);
            u.z = f2tf32(pa[c].z); u.w = f2tf32(pa[c].w);
            As4[st][(arow << 3) + (kc ^ (arow & 7))] = u;
        }
    };
    auto issueB = [&](int k0, int st) {
        uint32_t sb = (uint32_t)__cvta_generic_to_shared(&Bs4[st][0]);
        #pragma unroll
        for (int i = 0; i < 2; i++) {
            int cid = tid * 2 + i;
            int m  = cid >> 3;
            int kc = cid & 7;
            int gm = m0 + m, gk = k0 + kc * 4;
            const float* gp = B + (size_t)gm * ldb + gk;
            int ok = (gm < M && gk < K) ? 16 : 0;
            cp_async16(sb + (((m << 3) + (kc ^ (m & 7))) << 4), gp, ok);
        }
    };

    const int g  = lane >> 3;
    const int l7 = lane & 7;

    auto compute = [&](int st) {
        uint32_t aBase = (uint32_t)__cvta_generic_to_shared(&As4[st][0]);
        uint32_t bBase = (uint32_t)__cvta_generic_to_shared(&Bs4[st][0]);
        #pragma unroll
        for (int kb = 0; kb < 32; kb += 8) {
            const int kq = kb >> 2;
            uint32_t a[4][4];
            #pragma unroll
            for (int i = 0; i < 4; i++) {
                int row = wm + i * 16 + ((g & 1) << 3) + l7;
                int kc  = kq + (g >> 1);
                uint32_t ad = aBase + (((row << 3) + (kc ^ (row & 7))) << 4);
                ldsm_x4(a[i][0], a[i][1], a[i][2], a[i][3], ad);
            }
            uint32_t b[4];
            {
                int nrow = wn + ((g >> 1) << 3) + l7;
                int kc   = kq + (g & 1);
                uint32_t bd = bBase + (((nrow << 3) + (kc ^ (nrow & 7))) << 4);
                ldsm_x4(b[0], b[1], b[2], b[3], bd);
            }
            #pragma unroll
            for (int i = 0; i < 4; i++) {
                mma_tf32(acc[i][0], a[i], &b[0]);
                mma_tf32(acc[i][1], a[i], &b[2]);
            }
        }
    };

    const int T = (K + 31) / 32;

    loadA(0);
    issueB(0, 0);
    storeA(0);
    cp_commit(); cp_wait0();
    __syncthreads();

    for (int kt = 0; kt < T; kt++) {
        const int cur = kt & 1, nxt = cur ^ 1;
        const bool more = (kt + 1) < T;
        if (more) {
            loadA((kt + 1) * 32);
            issueB((kt + 1) * 32, nxt); cp_commit();
        }
        compute(cur);
        if (more) {
            storeA(nxt);
            cp_wait0();
            __syncthreads();
        }
    }

    if (SCATTER) {
        const int c0 = m0 + wn + (lane & 3) * 2;       // j=0 col pair
        const int c1 = c0 + 8;                          // j=1 col pair
        const bool p0 = (c0 + 1) < M;
        const bool p1 = (c1 + 1) < M;
        const bool s0 = c0 < M;
        const bool s1 = c1 < M;
        #pragma unroll
        for (int i = 0; i < 4; i++) {
            #pragma unroll
            for (int hrow = 0; hrow < 2; hrow++) {
                int r = n0 + wm + i * 16 + (lane >> 2) + hrow * 8;
                if (r >= N) continue;
                int pb = rowptr[r], pe = rowptr[r + 1];
                float v00 = acc[i][0][hrow * 2 + 0], v01 = acc[i][0][hrow * 2 + 1];
                float v10 = acc[i][1][hrow * 2 + 0], v11 = acc[i][1][hrow * 2 + 1];
                for (int p = pb; p < pe; p++) {
                    float* base = C + (size_t)dstidx[p] * CCH;
                    if (p0) red_v2(base + c0, v00, v01);
                    else if (s0) asm volatile("red.global.add.f32 [%0], %1;" :: "l"(base + c0), "f"(v00) : "memory");
                    if (p1) red_v2(base + c1, v10, v11);
                    else if (s1) asm volatile("red.global.add.f32 [%0], %1;" :: "l"(base + c1), "f"(v10) : "memory");
                }
            }
        }
    } else {
        #pragma unroll
        for (int i = 0; i < 4; i++) {
            #pragma unroll
            for (int j = 0; j < 2; j++) {
                int r0 = n0 + wm + i * 16 + (lane >> 2);
                int c0 = m0 + wn + j * 8 + (lane & 3) * 2;
                if (c0 >= M) continue;
                bool c1ok = (c0 + 1) < M;
                float bv0 = BIAS ? bias[c0] : 0.f;
                float bv1 = (BIAS && c1ok) ? bias[c0 + 1] : 0.f;
                #pragma unroll
                for (int hrow = 0; hrow < 2; hrow++) {
                    int r = r0 + hrow * 8;
                    if (r >= N) continue;
                    float v0 = acc[i][j][hrow * 2 + 0] + bv0;
                    float v1 = acc[i][j][hrow * 2 + 1] + bv1;
                    if (RELU) { v0 = fmaxf(v0, 0.f); v1 = fmaxf(v1, 0.f); }
                    if (c1ok && ((M & 1) == 0)) {
                        *reinterpret_cast<float2*>(C + (size_t)r * M + c0) = make_float2(v0, v1);
                    } else {
                        C[(size_t)r * M + c0] = v0;
                        if (c1ok) C[(size_t)r * M + c0 + 1] = v1;
                    }
                }
            }
        }
    }
}

// ---------------- fused GRU kernel: 128 rows x 64 cols, 512 threads (R12) ----------
#define GRU_STAGE_U4 5120
#define GRU_SMEM (2 * GRU_STAGE_U4 * 16)
template<int POOL>
__global__ __launch_bounds__(512, 1)
void gru_fused(const float* __restrict__ Aagg, const float* __restrict__ Ah,
               const float* __restrict__ Wih, const float* __restrict__ Whh,
               const float* __restrict__ bih, const float* __restrict__ bhh,
               float* __restrict__ hnew, int N,
               const int* __restrict__ batch, float* __restrict__ pool, int comp)
{
    extern __shared__ uint4 sm[];
    const int tid  = threadIdx.x;
    const int lane = tid & 31;
    const int wid  = tid >> 5;
    const int wm   = (wid & 3) * 32;
    const int wn   = (wid >> 2) * 16;
    const int n0   = blockIdx.x * 128;
    const int m0   = blockIdx.y * 64;

    float acc_i[3][2][2][4];
    float acc_h[3][2][2][4];
    #pragma unroll
    for (int gi = 0; gi < 3; gi++)
        #pragma unroll
        for (int i = 0; i < 2; i++)
            #pragma unroll
            for (int j = 0; j < 2; j++)
                #pragma unroll
                for (int q = 0; q < 4; q++) { acc_i[gi][i][j][q] = 0.f; acc_h[gi][i][j][q] = 0.f; }

    const int arow = tid >> 2;
    const int ac0  = (tid & 3) * 2;
    const bool arow_ok = (n0 + arow) < N;
    const float* Aggp = Aagg + (size_t)(n0 + arow) * CCH;
    const float* Ahp  = Ah   + (size_t)(n0 + arow) * CCH;

    float4 pagg[2], ph[2];

    auto loadA = [&](int k0) {
        #pragma unroll
        for (int c = 0; c < 2; c++) {
            int gk = k0 + (ac0 + c) * 4;
            pagg[c] = make_float4(0.f, 0.f, 0.f, 0.f);
            ph[c]   = make_float4(0.f, 0.f, 0.f, 0.f);
            if (arow_ok && gk < CCH) {
                pagg[c] = *reinterpret_cast<const float4*>(Aggp + gk);
                ph[c]   = *reinterpret_cast<const float4*>(Ahp + gk);
            }
        }
    };
    auto storeA = [&](int st) {
        uint4* Sa = sm + st * GRU_STAGE_U4;
        uint4* Sh = Sa + 1024;
        #pragma unroll
        for (int c = 0; c < 2; c++) {
            int kc = ac0 + c;
            int idx = (arow << 3) + (kc ^ (arow & 7));
            uint4 u;
            u.x = f2tf32(pagg[c].x); u.y = f2tf32(pagg[c].y);
            u.z = f2tf32(pagg[c].z); u.w = f2tf32(pagg[c].w);
            Sa[idx] = u;
            u.x = f2tf32(ph[c].x); u.y = f2tf32(ph[c].y);
            u.z = f2tf32(ph[c].z); u.w = f2tf32(ph[c].w);
            Sh[idx] = u;
        }
    };
    auto issueB = [&](int k0, int st) {
        uint32_t sb = (uint32_t)__cvta_generic_to_shared(sm + st * GRU_STAGE_U4 + 2048);
        const int row = tid >> 3;
        const int kc  = tid & 7;
        const int gm  = m0 + row;
        const int gk  = k0 + kc * 4;
        #pragma unroll
        for (int mat = 0; mat < 6; mat++) {
            const float* W = (mat < 3) ? Wih : Whh;
            int goff = (mat % 3) * CCH;
            int ok = (gm < CCH && gk < CCH) ? 16 : 0;
            cp_async16(sb + ((mat * 512 + (row << 3) + (kc ^ (row & 7))) << 4),
                       W + (size_t)(goff + gm) * CCH + gk, ok);
        }
    };

    const int g  = lane >> 3;
    const int l7 = lane & 7;

    auto compute = [&](int st) {
        uint32_t aBase = (uint32_t)__cvta_generic_to_shared(sm + st * GRU_STAGE_U4);
        uint32_t hBase = aBase + 1024 * 16;
        uint32_t bBase = aBase + 2048 * 16;
        #pragma unroll
        for (int kb = 0; kb < 32; kb += 8) {
            const int kq = kb >> 2;
            uint32_t ag[2][4], ah[2][4];
            #pragma unroll
            for (int i = 0; i < 2; i++) {
                int row = wm + i * 16 + ((g & 1) << 3) + l7;
                int kc  = kq + (g >> 1);
                uint32_t off = ((row << 3) + (kc ^ (row & 7))) << 4;
                ldsm_x4(ag[i][0], ag[i][1], ag[i][2], ag[i][3], aBase + off);
                ldsm_x4(ah[i][0], ah[i][1], ah[i][2], ah[i][3], hBase + off);
            }
            uint32_t b[6][4];
            {
                int nrow = wn + ((g >> 1) << 3) + l7;
                int kc   = kq + (g & 1);
                uint32_t off = ((nrow << 3) + (kc ^ (nrow & 7))) << 4;
                #pragma unroll
                for (int mat = 0; mat < 6; mat++)
                    ldsm_x4(b[mat][0], b[mat][1], b[mat][2], b[mat][3],
                            bBase + (mat * 512 << 4) + off);
            }
            #pragma unroll
            for (int gi = 0; gi < 3; gi++)
                #pragma unroll
                for (int i = 0; i < 2; i++) {
                    mma_tf32(acc_i[gi][i][0], ag[i], &b[gi][0]);
                    mma_tf32(acc_i[gi][i][1], ag[i], &b[gi][2]);
                    mma_tf32(acc_h[gi][i][0], ah[i], &b[3 + gi][0]);
                    mma_tf32(acc_h[gi][i][1], ah[i], &b[3 + gi][2]);
                }
        }
    };

    const int T = (CCH + 31) / 32;

    loadA(0); issueB(0, 0);
    storeA(0);
    cp_commit(); cp_wait0();
    __syncthreads();

    for (int kt = 0; kt < T; kt++) {
        const int cur = kt & 1, nxt = cur ^ 1;
        const bool more = (kt + 1) < T;
        if (more) {
            loadA((kt + 1) * 32);
            issueB((kt + 1) * 32, nxt);
            cp_commit();
        }
        compute(cur);
        if (more) {
            storeA(nxt);
            cp_wait0();
            __syncthreads();
        }
    }

    #pragma unroll
    for (int i = 0; i < 2; i++) {
        #pragma unroll
        for (int j = 0; j < 2; j++) {
            int rbase = n0 + wm + i * 16 + (lane >> 2);
            int c0 = m0 + wn + j * 8 + (lane & 3) * 2;
            #pragma unroll
            for (int q = 0; q < 2; q++) {
                int r = rbase + q * 8;
                if (r >= N) continue;
                #pragma unroll
                for (int p = 0; p < 2; p++) {
                    int c = c0 + p;
                    if (c >= CCH) continue;
                    int v = q * 2 + p;
                    float ir = acc_i[0][i][j][v] + bih[c];
                    float iz = acc_i[1][i][j][v] + bih[c + CCH];
                    float in = acc_i[2][i][j][v] + bih[c + 2 * CCH];
                    float hr = acc_h[0][i][j][v] + bhh[c];
                    float hz = acc_h[1][i][j][v] + bhh[c + CCH];
                    float hn = acc_h[2][i][j][v] + bhh[c + 2 * CCH];
                    float rg = sigm(ir + hr);
                    float z  = sigm(iz + hz);
                    float nn = tanhf(in + rg * hn);
                    float ho = Ah[(size_t)r * CCH + c];
                    float hv = (1.f - z) * nn + z * ho;
                    if (POOL) {
                        float pv = fmaxf(hv, 0.f);
                        float* pp = pool + (size_t)batch[r] * FCD + comp * CCH + c;
                        asm volatile("red.global.add.f32 [%0], %1;" :: "l"(pp), "f"(pv) : "memory");
                    } else {
                        hnew[(size_t)r * CCH + c] = hv;
                    }
                }
            }
        }
    }
}

// ---------------- CSR-by-src build kernels ----------------
__global__ void deg_count_kernel(const int* __restrict__ ei, int* __restrict__ deg, int E)
{
    int e = blockIdx.x * blockDim.x + threadIdx.x;
    if (e < E) atomicAdd(&deg[ei[e]], 1);      // keyed by src
}

__global__ __launch_bounds__(1024)
void scan_kernel(int* __restrict__ degc, int* __restrict__ rowptr, int N)
{
    __shared__ int warpsums[32];
    const int T = 1024;
    const int per = (N + T - 1) / T;
    const int start = threadIdx.x * per;
    int sum = 0;
    for (int i = 0; i < per; i++) {
        int idx = start + i;
        if (idx < N) sum += degc[idx];
    }
    int lane = threadIdx.x & 31, w = threadIdx.x >> 5;
    int v = sum;
    for (int o = 1; o < 32; o <<= 1) {
        int t = __shfl_up_sync(~0u, v, o);
        if (lane >= o) v += t;
    }
    if (lane == 31) warpsums[w] = v;
    __syncthreads();
    if (w == 0) {
        int u = warpsums[lane];
        for (int o = 1; o < 32; o <<= 1) {
            int t = __shfl_up_sync(~0u, u, o);
            if (lane >= o) u += t;
        }
        warpsums[lane] = u;
    }
    __syncthreads();
    int excl = v - sum + (w > 0 ? warpsums[w - 1] : 0);
    int run = excl;
    for (int i = 0; i < per; i++) {
        int idx = start + i;
        if (idx < N) {
            int d = degc[idx];
            rowptr[idx] = run;
            degc[idx] = run;
            run += d;
        }
    }
    if (threadIdx.x == T - 1) rowptr[N] = excl + sum;
}

__global__ void fill_kernel(const int* __restrict__ ei, int* __restrict__ cursor,
                            int* __restrict__ dstx, int E)
{
    int e = blockIdx.x * blockDim.x + threadIdx.x;
    if (e >= E) return;
    int src = ei[e];
    int pos = atomicAdd(&cursor[src], 1);
    dstx[pos] = ei[E + e];
}

// ---------------- weight pre-conversion ----------------
// conv weights: transpose [k][m] -> [m][k] with tf32 rounding (18 matrices of 180x180)
__global__ void cvt_tp_kernel(const float* __restrict__ in, float* __restrict__ out)
{
    int i = blockIdx.x * blockDim.x + threadIdx.x;
    if (i >= 18 * CCH * CCH) return;
    int mat = i / (CCH * CCH);
    int rem = i - mat * CCH * CCH;
    int m = rem / CCH, k = rem - m * CCH;
    out[i] = __uint_as_float(f2tf32(in[mat * CCH * CCH + k * CCH + m]));
}

__global__ void cvt_tf32_kernel(const float* __restrict__ in, float* __restrict__ out, int n)
{
    int i = blockIdx.x * blockDim.x + threadIdx.x;
    if (i < n) out[i] = __uint_as_float(f2tf32(in[i]));
}

// ---------------- elementwise / graph kernels ----------------
__global__ void pad_kernel(const float4* __restrict__ x, float4* __restrict__ h, int N, int F4)
{
    int i = blockIdx.x * blockDim.x + threadIdx.x;
    if (i >= N * 45) return;
    int n = i / 45, c = i - n * 45;
    float4 v = make_float4(0.f, 0.f, 0.f, 0.f);
    if (c < F4) v = x[(size_t)n * F4 + c];
    h[i] = v;
}

__global__ void zero_kernel(float4* __restrict__ p, int n4)
{
    int i = blockIdx.x * blockDim.x + threadIdx.x;
    if (i < n4) p[i] = make_float4(0.f, 0.f, 0.f, 0.f);
}

__global__ void count_kernel(const int* __restrict__ batch, float* __restrict__ cnt, int N)
{
    int i = blockIdx.x * blockDim.x + threadIdx.x;
    if (i < N) atomicAdd(&cnt[batch[i]], 1.f);
}

__global__ void bn_kernel(const float* __restrict__ pool, const float* __restrict__ cnt,
                          const float* __restrict__ gamma, const float* __restrict__ beta,
                          const float* __restrict__ mean, const float* __restrict__ var,
                          float* __restrict__ xout)
{
    int i = blockIdx.x * blockDim.x + threadIdx.x;
    if (i >= NGR * FCD) return;
    int b = i / FCD, j = i - b * FCD;
    int comp = j / CCH;
    float cn = fmaxf(cnt[comp * NGR + b], 1.f);
    float v = pool[i] / cn;
    v = (v - mean[j]) * rsqrtf(var[j] + 1e-5f) * gamma[j] + beta[j];
    xout[i] = v;
}

// ---------------- host orchestration ----------------
static inline void launch_gemm_scatter(const float* A, const float* B, float* agg,
                                       int N, int K, int M, int lda, int ldb,
                                       const int* rowptr, const int* dstx, cudaStream_t s)
{
    dim3 grid((N + 127) / 128, (M + 63) / 64);
    gemm_tf32<0, 0, 1><<<grid, 256, 0, s>>>(A, B, nullptr, agg, N, K, M, lda, ldb, rowptr, dstx);
}
template<int RELU>
static inline void launch_gemm_nt_bias(const float* A, const float* B, const float* bias,
                                       float* C, int N, int K, int M, cudaStream_t s)
{
    dim3 grid((N + 127) / 128, (M + 63) / 64);
    gemm_tf32<RELU, 1, 0><<<grid, 256, 0, s>>>(A, B, bias, C, N, K, M, K, K, nullptr, nullptr);
}

extern "C" void kernel_launch(void* const* d_in, const int* in_sizes, int n_in,
                              void* d_out, int out_size)
{
    static cudaStream_t cs[3] = {0, 0, 0};
    static cudaEvent_t ev_root = 0, ev_done[3] = {0, 0, 0};
    if (cs[0] == 0) {
        for (int i = 0; i < 3; i++) {
            cudaStreamCreateWithFlags(&cs[i], cudaStreamNonBlocking);
            cudaEventCreateWithFlags(&ev_done[i], cudaEventDisableTiming);
        }
        cudaEventCreateWithFlags(&ev_root, cudaEventDisableTiming);
        cudaFuncSetAttribute(gru_fused<0>, cudaFuncAttributeMaxDynamicSharedMemorySize, GRU_SMEM);
        cudaFuncSetAttribute(gru_fused<1>, cudaFuncAttributeMaxDynamicSharedMemorySize, GRU_SMEM);
    }
    cudaStream_t s0 = 0;

    const float* x[3]     = {(const float*)d_in[0], (const float*)d_in[3], (const float*)d_in[6]};
    const int*   ei[3]    = {(const int*)d_in[1], (const int*)d_in[4], (const int*)d_in[7]};
    const int*   batch[3] = {(const int*)d_in[2], (const int*)d_in[5], (const int*)d_in[8]};
    const float* convW = (const float*)d_in[9];
    const float* Wih   = (const float*)d_in[10];
    const float* Whh   = (const float*)d_in[11];
    const float* bih   = (const float*)d_in[12];
    const float* bhh   = (const float*)d_in[13];
    const float* bn_g  = (const float*)d_in[14];
    const float* bn_b  = (const float*)d_in[15];
    const float* bn_m  = (const float*)d_in[16];
    const float* bn_v  = (const float*)d_in[17];
    const float* fc1b  = (const float*)d_in[19];
    const float* fc2b  = (const float*)d_in[21];
    const float* fc25b = (const float*)d_in[23];
    const float* fc3b  = (const float*)d_in[25];

    const int N = in_sizes[2];
    const int E = in_sizes[1] / 2;
    const int F = in_sizes[0] / N;

    float *h_, *hn_, *agg_, *pool_, *cnt_, *x_, *b1_, *b2_, *wtf_;
    int *rowptr_, *cursor_, *dst_;
    cudaGetSymbolAddress((void**)&h_,   g_h);
    cudaGetSymbolAddress((void**)&hn_,  g_hn);
    cudaGetSymbolAddress((void**)&agg_, g_agg);
    cudaGetSymbolAddress((void**)&pool_,g_pool);
    cudaGetSymbolAddress((void**)&cnt_, g_cnt);
    cudaGetSymbolAddress((void**)&x_,   g_x);
    cudaGetSymbolAddress((void**)&b1_,  g_b1);
    cudaGetSymbolAddress((void**)&b2_,  g_b2);
    cudaGetSymbolAddress((void**)&wtf_, g_wtf);
    cudaGetSymbolAddress((void**)&rowptr_, g_rowptr);
    cudaGetSymbolAddress((void**)&cursor_, g_cursor);
    cudaGetSymbolAddress((void**)&dst_,    g_dst);

    const int TPB = 256;
    const int nNC4 = N * 45;
    const int gNC4 = (nNC4 + TPB - 1) / TPB;
    const int gE   = (E + TPB - 1) / TPB;

    // weight prep: conv TRANSPOSED+rounded (consumed NT as [m][k]); others rounded
    cvt_tp_kernel<<<(18 * CCH * CCH + 511) / 512, 512, 0, s0>>>(convW, wtf_ + OFF_CONV);
    {
        const float* fc1W  = (const float*)d_in[18];
        const float* fc2W  = (const float*)d_in[20];
        const float* fc25W = (const float*)d_in[22];
        const float* fc3W  = (const float*)d_in[24];
        struct { const float* src; int off; int n; } wl[6] = {
            {Wih,   OFF_WIH,  3 * FCD * CCH},
            {Whh,   OFF_WHH,  3 * FCD * CCH},
            {fc1W,  OFF_FC1,  HID * FCD},
            {fc2W,  OFF_FC2,  HID * HID},
            {fc25W, OFF_FC25, FCD * HID},
            {fc3W,  OFF_FC3,  3 * FCD},
        };
        for (int i = 0; i < 6; i++)
            cvt_tf32_kernel<<<(wl[i].n + 511) / 512, 512, 0, s0>>>(wl[i].src, wtf_ + wl[i].off, wl[i].n);
    }

    zero_kernel<<<(NGR * FCD / 4 + TPB - 1) / TPB, TPB, 0, s0>>>((float4*)pool_, NGR * FCD / 4);
    zero_kernel<<<(3 * NGR / 4 + TPB - 1) / TPB, TPB, 0, s0>>>((float4*)cnt_, 3 * NGR / 4);

    cudaEventRecord(ev_root, s0);

    const dim3 gruGrid((N + 127) / 128, 3);
    const size_t CS = (size_t)MAXN * CCH;

    for (int comp = 0; comp < 3; comp++) {
        cudaStream_t s = cs[comp];
        cudaStreamWaitEvent(s, ev_root, 0);

        float* hcur  = h_  + comp * CS;
        float* hnext = hn_ + comp * CS;
        float* ag    = agg_ + comp * CS;
        int* rp  = rowptr_ + comp * (MAXN + 1);
        int* cur = cursor_ + comp * (MAXN + 4);
        int* dsx = dst_    + comp * MAXE;

        // CSR-by-src build (once per component)
        zero_kernel<<<((N + 3) / 4 + TPB - 1) / TPB, TPB, 0, s>>>((float4*)cur, (N + 3) / 4);
        deg_count_kernel<<<gE, TPB, 0, s>>>(ei[comp], cur, E);
        scan_kernel<<<1, 1024, 0, s>>>(cur, rp, N);
        fill_kernel<<<gE, TPB, 0, s>>>(ei[comp], cur, dsx, E);

        pad_kernel<<<gNC4, TPB, 0, s>>>((const float4*)x[comp], (float4*)hcur, N, F / 4);
        const float* WihC = wtf_ + OFF_WIH + (size_t)comp * FCD * CCH;
        const float* WhhC = wtf_ + OFF_WHH + (size_t)comp * FCD * CCH;
        const float* bihC = bih + (size_t)comp * FCD;
        const float* bhhC = bhh + (size_t)comp * FCD;

        for (int l = 0; l < LNUM; l++) {
            const float* WlT = wtf_ + OFF_CONV + ((size_t)comp * LNUM + l) * CCH * CCH;  // [m][k]
            int Keff = (l == 0 && (F % 4) == 0 && F < CCH) ? F : CCH;
            zero_kernel<<<gNC4, TPB, 0, s>>>((float4*)ag, nNC4);
            // fused: m = h@Wl (NT on transposed weights) + scatter-to-agg epilogue
            launch_gemm_scatter(hcur, WlT, ag, N, Keff, CCH, CCH, CCH, rp, dsx, s);
            if (l < LNUM - 1) {
                gru_fused<0><<<gruGrid, 512, GRU_SMEM, s>>>(ag, hcur, WihC, WhhC, bihC, bhhC,
                                                            hnext, N, nullptr, nullptr, comp);
            } else {
                gru_fused<1><<<gruGrid, 512, GRU_SMEM, s>>>(ag, hcur, WihC, WhhC, bihC, bhhC,
                                                            nullptr, N, batch[comp], pool_, comp);
            }
            float* t = hcur; hcur = hnext; hnext = t;
        }
        count_kernel<<<(N + TPB - 1) / TPB, TPB, 0, s>>>(batch[comp], cnt_ + comp * NGR, N);
        cudaEventRecord(ev_done[comp], s);
    }

    for (int comp = 0; comp < 3; comp++)
        cudaStreamWaitEvent(s0, ev_done[comp], 0);

    bn_kernel<<<(NGR * FCD + TPB - 1) / TPB, TPB, 0, s0>>>(pool_, cnt_, bn_g, bn_b, bn_m, bn_v, x_);

    launch_gemm_nt_bias<1>(x_,  wtf_ + OFF_FC1,  fc1b,  b1_, NGR, FCD, HID, s0);
    launch_gemm_nt_bias<1>(b1_, wtf_ + OFF_FC2,  fc2b,  b2_, NGR, HID, HID, s0);
    launch_gemm_nt_bias<1>(b2_, wtf_ + OFF_FC25, fc25b, x_,  NGR, HID, FCD, s0);
    launch_gemm_nt_bias<0>(x_,  wtf_ + OFF_FC3,  fc3b,  (float*)d_out, NGR, FCD, 3, s0);
}